// round 9
// baseline (speedup 1.0000x reference)
#include <cuda_runtime.h>
#include <math.h>

#define B_ 4
#define C_ 64
#define H_ 128
#define W_ 128
#define O_ 64
#define HW_ (H_*W_)

// Scratch (static device globals -- allocation is forbidden)
__device__ float g_offs[(size_t)B_ * 18 * HW_];   // 18 offset channels per batch
__device__ float g_modmean[(size_t)B_ * HW_];     // mean of 9 sigmoids
__device__ float g_wT[9 * 64 * 64];               // weight, swizzled per-k (see k_wprep)

// ---- packed f32x2 helpers (sm_103a) ---------------------------------------
__device__ __forceinline__ unsigned long long pk2(float lo, float hi) {
    unsigned long long r;
    asm("mov.b64 %0, {%1, %2};" : "=l"(r) : "f"(lo), "f"(hi));
    return r;
}
__device__ __forceinline__ void upk2(unsigned long long v, float& lo, float& hi) {
    asm("mov.b64 {%0, %1}, %2;" : "=f"(lo), "=f"(hi) : "l"(v));
}
__device__ __forceinline__ void fma2(unsigned long long& d,
                                     unsigned long long a,
                                     unsigned long long b) {
    asm("fma.rn.f32x2 %0, %1, %2, %3;" : "=l"(d) : "l"(a), "l"(b), "l"(d));
}

// ---------------------------------------------------------------------------
// Prep: weight [O][C][9] -> g_wT[k][c][j] where j = q*16 + og*4 + e encodes
// o = og*16 + q*4 + e. The interleaving makes the 4 og-chunk LDS.128 reads
// in k_main conflict-free across lanes.
// ---------------------------------------------------------------------------
__global__ void k_wprep(const float* __restrict__ weight)
{
    int i = blockIdx.x * 256 + threadIdx.x;     // i = (k*64+c)*64 + j
    if (i >= 9 * 64 * 64) return;
    int j = i & 63;
    int kc = i >> 6;
    int c = kc & 63;
    int k = kc >> 6;
    int q  = j >> 4;
    int og = (j >> 2) & 3;
    int e  = j & 3;
    int o  = og * 16 + q * 4 + e;
    g_wT[i] = weight[((size_t)o * 64 + c) * 9 + k];
}

// ---------------------------------------------------------------------------
// Kernel 1: fused offset-conv (18ch) + modulation-conv (9ch) + sigmoid-mean.
// c processed in two halves of 32 so smem = 72KB -> 2 blocks/SM.
// Inner loop uses packed fma.rn.f32x2 (14 FFMA2 per (c,kk)).
// ---------------------------------------------------------------------------
__global__ __launch_bounds__(256, 2) void k_offmod(
    const float* __restrict__ x,
    const float* __restrict__ ow, const float* __restrict__ ob,
    const float* __restrict__ mw, const float* __restrict__ mb)
{
    extern __shared__ float sm1[];
    float* xs = sm1;                  // [32][18][18] : c_local*324 + y*18 + x
    float* wt = sm1 + 32 * 324;       // [(c_local*9+kk)][28] j-contiguous

    const int tid = threadIdx.x;
    const int tx = tid & 15, ty = tid >> 4;
    const int w0 = blockIdx.x * 16, h0 = blockIdx.y * 16;
    const int b = blockIdx.z;
    const float* xb = x + (size_t)b * C_ * HW_;

    unsigned long long acc2[14];
#pragma unroll
    for (int q = 0; q < 14; ++q) acc2[q] = 0ull;

    for (int half = 0; half < 2; ++half) {
        __syncthreads();
        // x tile chunk (32 channels); conv uses zero padding -> zero OOB
        for (int i = tid; i < 32 * 324; i += 256) {
            int c = i / 324, r = i % 324;
            int yy = r / 18, xx = r % 18;
            int gy = h0 + yy - 1, gx = w0 + xx - 1;
            float v = 0.f;
            if (gy >= 0 && gy < H_ && gx >= 0 && gx < W_)
                v = xb[(size_t)(half * 32 + c) * HW_ + gy * W_ + gx];
            xs[i] = v;
        }
        // weight chunk: wt[(c_local*9+kk)*28 + j]
        for (int i = tid; i < 32 * 9 * 28; i += 256) {
            int j = i % 28;
            int ckl = i / 28;                 // c_local*9+kk in [0,288)
            int ck = half * 288 + ckl;        // global c*9+kk
            float v = 0.f;
            if (j < 18)       v = ow[(size_t)j * 576 + ck];
            else if (j < 27)  v = mw[(size_t)(j - 18) * 576 + ck];
            wt[i] = v;
        }
        __syncthreads();

        for (int c = 0; c < 32; ++c) {
#pragma unroll
            for (int kk = 0; kk < 9; ++kk) {
                const int ky = kk / 3, kx = kk % 3;
                const float xv = xs[c * 324 + (ty + ky) * 18 + (tx + kx)];
                const unsigned long long xv2 = pk2(xv, xv);
                const ulonglong2* wr =
                    reinterpret_cast<const ulonglong2*>(wt + (c * 9 + kk) * 28);
#pragma unroll
                for (int p = 0; p < 7; ++p) {
                    ulonglong2 wp = wr[p];
                    fma2(acc2[2 * p + 0], xv2, wp.x);
                    fma2(acc2[2 * p + 1], xv2, wp.y);
                }
            }
        }
    }

    const int h = h0 + ty, w = w0 + tx;
    const int hw = h * W_ + w;
    float accs[28];
#pragma unroll
    for (int q = 0; q < 14; ++q) upk2(acc2[q], accs[2 * q], accs[2 * q + 1]);

#pragma unroll
    for (int j = 0; j < 18; ++j)
        g_offs[((size_t)b * 18 + j) * HW_ + hw] = accs[j] + __ldg(&ob[j]);

    float s = 0.f;
#pragma unroll
    for (int j = 0; j < 9; ++j) {
        float z = accs[18 + j] + __ldg(&mb[j]);
        s += 1.f / (1.f + __expf(-z));
    }
    g_modmean[(size_t)b * HW_ + hw] = s * (1.f / 9.f);
}

// ---------------------------------------------------------------------------
// Kernel 2 (v5): v4 + double-buffered weights (1 barrier per k-tap, staging
// overlapped with compute) + gather prefetch distance 1 (LDGs for c+1 issued
// before consuming c's values).
// Block = 32x8 px tile, 8 warps; warp = one image row of 32 px.
// smem = 32KB (2 weight buffers), 2 blocks/SM.
// ---------------------------------------------------------------------------
__global__ __launch_bounds__(256, 2) void k_main(
    const float* __restrict__ x,
    const float* __restrict__ bias,
    float* __restrict__ out)
{
    __shared__ float wk[2][64 * 64];   // [buf][c][j] swizzled (q*16 + og*4 + e)

    const int tid = threadIdx.x;
    const int wid = tid >> 5, lane = tid & 31;
    const int quad = lane >> 2, og = lane & 3;
    const int b = blockIdx.z;
    const int w0 = blockIdx.x * 32, h0 = blockIdx.y * 8;
    const int h = h0 + wid;
    const int aw = w0 + lane;          // gather identity: own pixel
    const int ahw = h * W_ + aw;
    const int bw = w0 + quad * 4;      // GEMM identity: quad of pixels
    const int bhw0 = h * W_ + bw;
    const float* xb = x + (size_t)b * C_ * HW_;
    const int qb = lane & ~3;          // quad base lane

    unsigned long long acc2[4][8];     // [px][2*q+p] <-> o = og*16 + 4q + 2p
#pragma unroll
    for (int i = 0; i < 4; ++i)
#pragma unroll
        for (int q = 0; q < 8; ++q) acc2[i][q] = 0ull;

    // stage weights for k=0 into buffer 0
    {
        const float4* src = reinterpret_cast<const float4*>(g_wT);
        float4* dst = reinterpret_cast<float4*>(wk[0]);
#pragma unroll
        for (int i = 0; i < 4; ++i) dst[tid + 256 * i] = src[tid + 256 * i];
    }
    __syncthreads();

    for (int k = 0; k < 9; ++k) {
        const float* wcur = wk[k & 1];

        // kick off staging of k+1 weights into the other buffer (no sync;
        // the barrier at the end of this iteration publishes them)
        if (k < 8) {
            const float4* src =
                reinterpret_cast<const float4*>(g_wT + (k + 1) * 4096);
            float4* dst = reinterpret_cast<float4*>(wk[(k + 1) & 1]);
#pragma unroll
            for (int i = 0; i < 4; ++i) dst[tid + 256 * i] = src[tid + 256 * i];
        }

        // bilinear setup for this lane's pixel
        const int ky = k / 3 - 1, kx = k % 3 - 1;
        const float sy = (float)(h + ky)
            + g_offs[((size_t)b * 18 + k) * HW_ + ahw];
        const float sx = (float)(aw + kx)
            + g_offs[((size_t)b * 18 + 9 + k) * HW_ + ahw];
        const float y0f = floorf(sy), x0f = floorf(sx);
        const float wy1 = sy - y0f, wx1 = sx - x0f;
        const float wy0 = 1.f - wy1, wx0 = 1.f - wx1;
        const int y0 = (int)y0f, x0 = (int)x0f;
        const bool vy0 = (y0 >= 0) & (y0 < H_);
        const bool vy1 = (y0 + 1 >= 0) & (y0 + 1 < H_);
        const bool vx0 = (x0 >= 0) & (x0 < W_);
        const bool vx1 = (x0 + 1 >= 0) & (x0 + 1 < W_);
        const float m00 = (vy0 && vx0) ? wy0 * wx0 : 0.f;
        const float m01 = (vy0 && vx1) ? wy0 * wx1 : 0.f;
        const float m10 = (vy1 && vx0) ? wy1 * wx0 : 0.f;
        const float m11 = (vy1 && vx1) ? wy1 * wx1 : 0.f;
        const int cy0 = min(max(y0, 0), H_ - 1);
        const int cy1 = min(max(y0 + 1, 0), H_ - 1);
        const int cx0 = min(max(x0, 0), W_ - 1);
        const int cx1 = min(max(x0 + 1, 0), W_ - 1);
        const int i00 = cy0 * W_ + cx0, i01 = cy0 * W_ + cx1;
        const int i10 = cy1 * W_ + cx0, i11 = cy1 * W_ + cx1;

        // prefetch corners for c=0
        float p00 = __ldg(xb + i00), p01 = __ldg(xb + i01);
        float p10 = __ldg(xb + i10), p11 = __ldg(xb + i11);

#pragma unroll 4
        for (int c = 0; c < 64; ++c) {
            // prefetch corners for c+1 (dead for c==63, masked cheaply)
            float n00 = 0.f, n01 = 0.f, n10 = 0.f, n11 = 0.f;
            if (c < 63) {
                const float* xn = xb + (size_t)(c + 1) * HW_;
                n00 = __ldg(xn + i00); n01 = __ldg(xn + i01);
                n10 = __ldg(xn + i10); n11 = __ldg(xn + i11);
            }

            const float v = m00 * p00 + m01 * p01 + m10 * p10 + m11 * p11;
            // warp-local transpose: broadcast quad's 4 pixel values
            const float v0f = __shfl_sync(0xffffffffu, v, qb + 0);
            const float v1f = __shfl_sync(0xffffffffu, v, qb + 1);
            const float v2f = __shfl_sync(0xffffffffu, v, qb + 2);
            const float v3f = __shfl_sync(0xffffffffu, v, qb + 3);
            const unsigned long long v0 = pk2(v0f, v0f);
            const unsigned long long v1 = pk2(v1f, v1f);
            const unsigned long long v2 = pk2(v2f, v2f);
            const unsigned long long v3 = pk2(v3f, v3f);

            const float* wc = wcur + c * 64 + og * 4;
            const ulonglong2 wA = *reinterpret_cast<const ulonglong2*>(wc);
            const ulonglong2 wB = *reinterpret_cast<const ulonglong2*>(wc + 16);
            const ulonglong2 wC = *reinterpret_cast<const ulonglong2*>(wc + 32);
            const ulonglong2 wD = *reinterpret_cast<const ulonglong2*>(wc + 48);

            fma2(acc2[0][0], v0, wA.x); fma2(acc2[0][1], v0, wA.y);
            fma2(acc2[0][2], v0, wB.x); fma2(acc2[0][3], v0, wB.y);
            fma2(acc2[0][4], v0, wC.x); fma2(acc2[0][5], v0, wC.y);
            fma2(acc2[0][6], v0, wD.x); fma2(acc2[0][7], v0, wD.y);
            fma2(acc2[1][0], v1, wA.x); fma2(acc2[1][1], v1, wA.y);
            fma2(acc2[1][2], v1, wB.x); fma2(acc2[1][3], v1, wB.y);
            fma2(acc2[1][4], v1, wC.x); fma2(acc2[1][5], v1, wC.y);
            fma2(acc2[1][6], v1, wD.x); fma2(acc2[1][7], v1, wD.y);
            fma2(acc2[2][0], v2, wA.x); fma2(acc2[2][1], v2, wA.y);
            fma2(acc2[2][2], v2, wB.x); fma2(acc2[2][3], v2, wB.y);
            fma2(acc2[2][4], v2, wC.x); fma2(acc2[2][5], v2, wC.y);
            fma2(acc2[2][6], v2, wD.x); fma2(acc2[2][7], v2, wD.y);
            fma2(acc2[3][0], v3, wA.x); fma2(acc2[3][1], v3, wA.y);
            fma2(acc2[3][2], v3, wB.x); fma2(acc2[3][3], v3, wB.y);
            fma2(acc2[3][4], v3, wC.x); fma2(acc2[3][5], v3, wC.y);
            fma2(acc2[3][6], v3, wD.x); fma2(acc2[3][7], v3, wD.y);

            p00 = n00; p01 = n01; p10 = n10; p11 = n11;
        }

        __syncthreads();   // publish next wk buffer; cur fully consumed
    }

    // epilogue: acc2[i][2q+p] holds o = og*16 + 4q + 2p (+1 in hi half)
    float mm[4];
#pragma unroll
    for (int i = 0; i < 4; ++i) mm[i] = g_modmean[(size_t)b * HW_ + bhw0 + i];

#pragma unroll
    for (int q = 0; q < 4; ++q) {
#pragma unroll
        for (int p = 0; p < 2; ++p) {
            float a0[4], a1[4];
#pragma unroll
            for (int i = 0; i < 4; ++i) upk2(acc2[i][2 * q + p], a0[i], a1[i]);
            const int oa = og * 16 + 4 * q + 2 * p, ob2 = oa + 1;
            const float ba = __ldg(&bias[oa]), bb = __ldg(&bias[ob2]);
            float4 va, vb;
            va.x = fmaf(a0[0], mm[0], ba); va.y = fmaf(a0[1], mm[1], ba);
            va.z = fmaf(a0[2], mm[2], ba); va.w = fmaf(a0[3], mm[3], ba);
            vb.x = fmaf(a1[0], mm[0], bb); vb.y = fmaf(a1[1], mm[1], bb);
            vb.z = fmaf(a1[2], mm[2], bb); vb.w = fmaf(a1[3], mm[3], bb);
            *reinterpret_cast<float4*>(out + ((size_t)b * 64 + oa) * HW_ + bhw0) = va;
            *reinterpret_cast<float4*>(out + ((size_t)b * 64 + ob2) * HW_ + bhw0) = vb;
        }
    }
}

// ---------------------------------------------------------------------------
extern "C" void kernel_launch(void* const* d_in, const int* in_sizes, int n_in,
                              void* d_out, int out_size)
{
    const float* x      = (const float*)d_in[0];
    const float* weight = (const float*)d_in[1];
    const float* bias   = (const float*)d_in[2];
    const float* ow     = (const float*)d_in[3];
    const float* ob     = (const float*)d_in[4];
    const float* mw     = (const float*)d_in[5];
    const float* mb     = (const float*)d_in[6];
    float* out = (float*)d_out;

    const size_t sm_off = (size_t)(32 * 324 + 32 * 9 * 28) * sizeof(float); // 73728
    cudaFuncSetAttribute(k_offmod, cudaFuncAttributeMaxDynamicSharedMemorySize,
                         (int)sm_off);

    k_wprep<<<(9 * 64 * 64 + 255) / 256, 256>>>(weight);

    dim3 grd_off(W_ / 16, H_ / 16, B_);
    k_offmod<<<grd_off, 256, sm_off>>>(x, ow, ob, mw, mb);

    dim3 grd_main(W_ / 32, H_ / 8, B_);
    k_main<<<grd_main, 256>>>(x, bias, out);
}

// round 13
// speedup vs baseline: 1.0577x; 1.0577x over previous
#include <cuda_runtime.h>
#include <math.h>

#define B_ 4
#define C_ 64
#define H_ 128
#define W_ 128
#define O_ 64
#define HW_ (H_*W_)

// Scratch (static device globals -- allocation is forbidden)
__device__ float g_offs[(size_t)B_ * 18 * HW_];   // 18 offset channels per batch
__device__ float g_modmean[(size_t)B_ * HW_];     // mean of 9 sigmoids
__device__ float g_wT[9 * 64 * 64];               // weight, swizzled per-k (see k_wprep)

// ---- packed f32x2 helpers (sm_103a) ---------------------------------------
__device__ __forceinline__ unsigned long long pk2(float lo, float hi) {
    unsigned long long r;
    asm("mov.b64 %0, {%1, %2};" : "=l"(r) : "f"(lo), "f"(hi));
    return r;
}
__device__ __forceinline__ void upk2(unsigned long long v, float& lo, float& hi) {
    asm("mov.b64 {%0, %1}, %2;" : "=f"(lo), "=f"(hi) : "l"(v));
}
__device__ __forceinline__ void fma2(unsigned long long& d,
                                     unsigned long long a,
                                     unsigned long long b) {
    asm("fma.rn.f32x2 %0, %1, %2, %3;" : "=l"(d) : "l"(a), "l"(b), "l"(d));
}

// ---------------------------------------------------------------------------
// Prep: weight [O][C][9] -> g_wT[k][c][j] where j = q*16 + og*4 + e encodes
// o = og*16 + q*4 + e. The interleaving makes the 4 og-chunk LDS.128 reads
// in k_main conflict-free across lanes.
// ---------------------------------------------------------------------------
__global__ void k_wprep(const float* __restrict__ weight)
{
    int i = blockIdx.x * 256 + threadIdx.x;     // i = (k*64+c)*64 + j
    if (i >= 9 * 64 * 64) return;
    int j = i & 63;
    int kc = i >> 6;
    int c = kc & 63;
    int k = kc >> 6;
    int q  = j >> 4;
    int og = (j >> 2) & 3;
    int e  = j & 3;
    int o  = og * 16 + q * 4 + e;
    g_wT[i] = weight[((size_t)o * 64 + c) * 9 + k];
}

// ---------------------------------------------------------------------------
// Kernel 1: fused offset-conv (18ch) + modulation-conv (9ch) + sigmoid-mean.
// c processed in two halves of 32 so smem = 72KB; minblocks=3 allows
// 3 blocks/SM (221KB smem, 85-reg cap) for better latency hiding; falls
// back to 2 harmlessly if ptxas needs more registers.
// Inner loop uses packed fma.rn.f32x2 (14 FFMA2 per (c,kk)).
// ---------------------------------------------------------------------------
__global__ __launch_bounds__(256, 3) void k_offmod(
    const float* __restrict__ x,
    const float* __restrict__ ow, const float* __restrict__ ob,
    const float* __restrict__ mw, const float* __restrict__ mb)
{
    extern __shared__ float sm1[];
    float* xs = sm1;                  // [32][18][18] : c_local*324 + y*18 + x
    float* wt = sm1 + 32 * 324;       // [(c_local*9+kk)][28] j-contiguous

    const int tid = threadIdx.x;
    const int tx = tid & 15, ty = tid >> 4;
    const int w0 = blockIdx.x * 16, h0 = blockIdx.y * 16;
    const int b = blockIdx.z;
    const float* xb = x + (size_t)b * C_ * HW_;

    unsigned long long acc2[14];
#pragma unroll
    for (int q = 0; q < 14; ++q) acc2[q] = 0ull;

    for (int half = 0; half < 2; ++half) {
        __syncthreads();
        // x tile chunk (32 channels); conv uses zero padding -> zero OOB
        for (int i = tid; i < 32 * 324; i += 256) {
            int c = i / 324, r = i % 324;
            int yy = r / 18, xx = r % 18;
            int gy = h0 + yy - 1, gx = w0 + xx - 1;
            float v = 0.f;
            if (gy >= 0 && gy < H_ && gx >= 0 && gx < W_)
                v = xb[(size_t)(half * 32 + c) * HW_ + gy * W_ + gx];
            xs[i] = v;
        }
        // weight chunk: wt[(c_local*9+kk)*28 + j]
        for (int i = tid; i < 32 * 9 * 28; i += 256) {
            int j = i % 28;
            int ckl = i / 28;                 // c_local*9+kk in [0,288)
            int ck = half * 288 + ckl;        // global c*9+kk
            float v = 0.f;
            if (j < 18)       v = ow[(size_t)j * 576 + ck];
            else if (j < 27)  v = mw[(size_t)(j - 18) * 576 + ck];
            wt[i] = v;
        }
        __syncthreads();

        for (int c = 0; c < 32; ++c) {
#pragma unroll
            for (int kk = 0; kk < 9; ++kk) {
                const int ky = kk / 3, kx = kk % 3;
                const float xv = xs[c * 324 + (ty + ky) * 18 + (tx + kx)];
                const unsigned long long xv2 = pk2(xv, xv);
                const ulonglong2* wr =
                    reinterpret_cast<const ulonglong2*>(wt + (c * 9 + kk) * 28);
#pragma unroll
                for (int p = 0; p < 7; ++p) {
                    ulonglong2 wp = wr[p];
                    fma2(acc2[2 * p + 0], xv2, wp.x);
                    fma2(acc2[2 * p + 1], xv2, wp.y);
                }
            }
        }
    }

    const int h = h0 + ty, w = w0 + tx;
    const int hw = h * W_ + w;
    float accs[28];
#pragma unroll
    for (int q = 0; q < 14; ++q) upk2(acc2[q], accs[2 * q], accs[2 * q + 1]);

#pragma unroll
    for (int j = 0; j < 18; ++j)
        g_offs[((size_t)b * 18 + j) * HW_ + hw] = accs[j] + __ldg(&ob[j]);

    float s = 0.f;
#pragma unroll
    for (int j = 0; j < 9; ++j) {
        float z = accs[18 + j] + __ldg(&mb[j]);
        s += 1.f / (1.f + __expf(-z));
    }
    g_modmean[(size_t)b * HW_ + hw] = s * (1.f / 9.f);
}

// ---------------------------------------------------------------------------
// Kernel 2 (v4): warp-local gather+GEMM, no S array, no phase barriers.
// Block = 32x8 px tile, 8 warps; warp = one image row of 32 px.
// Per c: lane gathers v for its own pixel (4 masked LDG, exact for any
// offset), the 4 lanes of each quad exchange v via shfl, then each lane
// (quad, og) does 32 FFMA2 against its 16-output weight chunk from smem.
// smem = 16KB (weights only), 2 blocks/SM.
// ---------------------------------------------------------------------------
__global__ __launch_bounds__(256, 2) void k_main(
    const float* __restrict__ x,
    const float* __restrict__ bias,
    float* __restrict__ out)
{
    __shared__ float wk[64 * 64];      // [c][j] swizzled (q*16 + og*4 + e)

    const int tid = threadIdx.x;
    const int wid = tid >> 5, lane = tid & 31;
    const int quad = lane >> 2, og = lane & 3;
    const int b = blockIdx.z;
    const int w0 = blockIdx.x * 32, h0 = blockIdx.y * 8;
    const int h = h0 + wid;
    const int aw = w0 + lane;          // gather identity: own pixel
    const int ahw = h * W_ + aw;
    const int bw = w0 + quad * 4;      // GEMM identity: quad of pixels
    const int bhw0 = h * W_ + bw;
    const float* xb = x + (size_t)b * C_ * HW_;

    unsigned long long acc2[4][8];     // [px][2*q+p] <-> o = og*16 + 4q + 2p
#pragma unroll
    for (int i = 0; i < 4; ++i)
#pragma unroll
        for (int q = 0; q < 8; ++q) acc2[i][q] = 0ull;

    for (int k = 0; k < 9; ++k) {
        __syncthreads();               // previous wk fully consumed
        // stage weights for this k (already swizzled in g_wT)
        {
            const float4* src = reinterpret_cast<const float4*>(g_wT + k * 4096);
            float4* dst = reinterpret_cast<float4*>(wk);
#pragma unroll
            for (int i = 0; i < 4; ++i) dst[tid + 256 * i] = src[tid + 256 * i];
        }
        __syncthreads();

        // bilinear setup for this lane's pixel
        const int ky = k / 3 - 1, kx = k % 3 - 1;
        const float sy = (float)(h + ky)
            + g_offs[((size_t)b * 18 + k) * HW_ + ahw];
        const float sx = (float)(aw + kx)
            + g_offs[((size_t)b * 18 + 9 + k) * HW_ + ahw];
        const float y0f = floorf(sy), x0f = floorf(sx);
        const float wy1 = sy - y0f, wx1 = sx - x0f;
        const float wy0 = 1.f - wy1, wx0 = 1.f - wx1;
        const int y0 = (int)y0f, x0 = (int)x0f;
        const bool vy0 = (y0 >= 0) & (y0 < H_);
        const bool vy1 = (y0 + 1 >= 0) & (y0 + 1 < H_);
        const bool vx0 = (x0 >= 0) & (x0 < W_);
        const bool vx1 = (x0 + 1 >= 0) & (x0 + 1 < W_);
        const float m00 = (vy0 && vx0) ? wy0 * wx0 : 0.f;
        const float m01 = (vy0 && vx1) ? wy0 * wx1 : 0.f;
        const float m10 = (vy1 && vx0) ? wy1 * wx0 : 0.f;
        const float m11 = (vy1 && vx1) ? wy1 * wx1 : 0.f;
        const int cy0 = min(max(y0, 0), H_ - 1);
        const int cy1 = min(max(y0 + 1, 0), H_ - 1);
        const int cx0 = min(max(x0, 0), W_ - 1);
        const int cx1 = min(max(x0 + 1, 0), W_ - 1);
        const int i00 = cy0 * W_ + cx0, i01 = cy0 * W_ + cx1;
        const int i10 = cy1 * W_ + cx0, i11 = cy1 * W_ + cx1;
        const int qb = lane & ~3;      // quad base lane

#pragma unroll 4
        for (int c = 0; c < 64; ++c) {
            const float* xc = xb + (size_t)c * HW_;
            const float v = m00 * __ldg(xc + i00) + m01 * __ldg(xc + i01)
                          + m10 * __ldg(xc + i10) + m11 * __ldg(xc + i11);
            // warp-local transpose: broadcast quad's 4 pixel values
            const float v0f = __shfl_sync(0xffffffffu, v, qb + 0);
            const float v1f = __shfl_sync(0xffffffffu, v, qb + 1);
            const float v2f = __shfl_sync(0xffffffffu, v, qb + 2);
            const float v3f = __shfl_sync(0xffffffffu, v, qb + 3);
            const unsigned long long v0 = pk2(v0f, v0f);
            const unsigned long long v1 = pk2(v1f, v1f);
            const unsigned long long v2 = pk2(v2f, v2f);
            const unsigned long long v3 = pk2(v3f, v3f);

            const float* wc = wk + c * 64 + og * 4;
            const ulonglong2 wA = *reinterpret_cast<const ulonglong2*>(wc);
            const ulonglong2 wB = *reinterpret_cast<const ulonglong2*>(wc + 16);
            const ulonglong2 wC = *reinterpret_cast<const ulonglong2*>(wc + 32);
            const ulonglong2 wD = *reinterpret_cast<const ulonglong2*>(wc + 48);

            fma2(acc2[0][0], v0, wA.x); fma2(acc2[0][1], v0, wA.y);
            fma2(acc2[0][2], v0, wB.x); fma2(acc2[0][3], v0, wB.y);
            fma2(acc2[0][4], v0, wC.x); fma2(acc2[0][5], v0, wC.y);
            fma2(acc2[0][6], v0, wD.x); fma2(acc2[0][7], v0, wD.y);
            fma2(acc2[1][0], v1, wA.x); fma2(acc2[1][1], v1, wA.y);
            fma2(acc2[1][2], v1, wB.x); fma2(acc2[1][3], v1, wB.y);
            fma2(acc2[1][4], v1, wC.x); fma2(acc2[1][5], v1, wC.y);
            fma2(acc2[1][6], v1, wD.x); fma2(acc2[1][7], v1, wD.y);
            fma2(acc2[2][0], v2, wA.x); fma2(acc2[2][1], v2, wA.y);
            fma2(acc2[2][2], v2, wB.x); fma2(acc2[2][3], v2, wB.y);
            fma2(acc2[2][4], v2, wC.x); fma2(acc2[2][5], v2, wC.y);
            fma2(acc2[2][6], v2, wD.x); fma2(acc2[2][7], v2, wD.y);
            fma2(acc2[3][0], v3, wA.x); fma2(acc2[3][1], v3, wA.y);
            fma2(acc2[3][2], v3, wB.x); fma2(acc2[3][3], v3, wB.y);
            fma2(acc2[3][4], v3, wC.x); fma2(acc2[3][5], v3, wC.y);
            fma2(acc2[3][6], v3, wD.x); fma2(acc2[3][7], v3, wD.y);
        }
    }

    // epilogue: acc2[i][2q+p] holds o = og*16 + 4q + 2p (+1 in hi half)
    float mm[4];
#pragma unroll
    for (int i = 0; i < 4; ++i) mm[i] = g_modmean[(size_t)b * HW_ + bhw0 + i];

#pragma unroll
    for (int q = 0; q < 4; ++q) {
#pragma unroll
        for (int p = 0; p < 2; ++p) {
            float a0[4], a1[4];
#pragma unroll
            for (int i = 0; i < 4; ++i) upk2(acc2[i][2 * q + p], a0[i], a1[i]);
            const int oa = og * 16 + 4 * q + 2 * p, ob2 = oa + 1;
            const float ba = __ldg(&bias[oa]), bb = __ldg(&bias[ob2]);
            float4 va, vb;
            va.x = fmaf(a0[0], mm[0], ba); va.y = fmaf(a0[1], mm[1], ba);
            va.z = fmaf(a0[2], mm[2], ba); va.w = fmaf(a0[3], mm[3], ba);
            vb.x = fmaf(a1[0], mm[0], bb); vb.y = fmaf(a1[1], mm[1], bb);
            vb.z = fmaf(a1[2], mm[2], bb); vb.w = fmaf(a1[3], mm[3], bb);
            *reinterpret_cast<float4*>(out + ((size_t)b * 64 + oa) * HW_ + bhw0) = va;
            *reinterpret_cast<float4*>(out + ((size_t)b * 64 + ob2) * HW_ + bhw0) = vb;
        }
    }
}

// ---------------------------------------------------------------------------
// Launch order: k_offmod first (lands in the ncu capture slot), then
// k_wprep (depends only on weight), then k_main (needs g_offs + g_wT).
// ---------------------------------------------------------------------------
extern "C" void kernel_launch(void* const* d_in, const int* in_sizes, int n_in,
                              void* d_out, int out_size)
{
    const float* x      = (const float*)d_in[0];
    const float* weight = (const float*)d_in[1];
    const float* bias   = (const float*)d_in[2];
    const float* ow     = (const float*)d_in[3];
    const float* ob     = (const float*)d_in[4];
    const float* mw     = (const float*)d_in[5];
    const float* mb     = (const float*)d_in[6];
    float* out = (float*)d_out;

    const size_t sm_off = (size_t)(32 * 324 + 32 * 9 * 28) * sizeof(float); // 73728
    cudaFuncSetAttribute(k_offmod, cudaFuncAttributeMaxDynamicSharedMemorySize,
                         (int)sm_off);

    dim3 grd_off(W_ / 16, H_ / 16, B_);
    k_offmod<<<grd_off, 256, sm_off>>>(x, ow, ob, mw, mb);

    k_wprep<<<(9 * 64 * 64 + 255) / 256, 256>>>(weight);

    dim3 grd_main(W_ / 32, H_ / 8, B_);
    k_main<<<grd_main, 256>>>(x, bias, out);
}

// round 14
// speedup vs baseline: 1.0786x; 1.0198x over previous
#include <cuda_runtime.h>
#include <math.h>

#define B_ 4
#define C_ 64
#define H_ 128
#define W_ 128
#define O_ 64
#define HW_ (H_*W_)

// Scratch (static device globals -- allocation is forbidden)
__device__ float g_offs[(size_t)B_ * 18 * HW_];   // 18 offset channels per batch
__device__ float g_modmean[(size_t)B_ * HW_];     // mean of 9 sigmoids
__device__ float g_wT[9 * 64 * 64];               // main weight, swizzled per-k

// ---- packed f32x2 helpers (sm_103a) ---------------------------------------
__device__ __forceinline__ unsigned long long pk2(float lo, float hi) {
    unsigned long long r;
    asm("mov.b64 %0, {%1, %2};" : "=l"(r) : "f"(lo), "f"(hi));
    return r;
}
__device__ __forceinline__ void upk2(unsigned long long v, float& lo, float& hi) {
    asm("mov.b64 {%0, %1}, %2;" : "=f"(lo), "=f"(hi) : "l"(v));
}
__device__ __forceinline__ void fma2(unsigned long long& d,
                                     unsigned long long a,
                                     unsigned long long b) {
    asm("fma.rn.f32x2 %0, %1, %2, %3;" : "=l"(d) : "l"(a), "l"(b), "l"(d));
}

// ---------------------------------------------------------------------------
// Prep: weight [O][C][9] -> g_wT[k][c][j] where j = q*16 + og*4 + e encodes
// o = og*16 + q*4 + e (conflict-free og-chunk LDS.128 in k_main).
// ---------------------------------------------------------------------------
__global__ void k_wprep(const float* __restrict__ weight)
{
    int i = blockIdx.x * 256 + threadIdx.x;     // i = (k*64+c)*64 + j
    if (i >= 9 * 64 * 64) return;
    int j = i & 63;
    int kc = i >> 6;
    int c = kc & 63;
    int k = kc >> 6;
    int q  = j >> 4;
    int og = (j >> 2) & 3;
    int e  = j & 3;
    int o  = og * 16 + q * 4 + e;
    g_wT[i] = weight[((size_t)o * 64 + c) * 9 + k];
}

// ---------------------------------------------------------------------------
// Kernel 1 (v2): offset-conv (18ch) + mod-conv (9ch) + sigmoid-mean, in the
// proven k_main structure. Block = 32x8 tile, warp = image row of 32 px.
// Per (c,kk): lane gathers its own pixel's xv via 1 zero-masked LDG, quad
// shfl-broadcasts 4 px, each lane (quad, jg) does 2 LDS.128 (8 j-weights,
// 28 channels padded to 32) + 16 FFMA2.
// Weights staged per c-half into 36.9KB smem directly from ow/mw.
// j layout: j<18 offset channels, 18..26 modulation, 27..31 zero pad.
// ---------------------------------------------------------------------------
__global__ __launch_bounds__(256, 3) void k_offmod(
    const float* __restrict__ x,
    const float* __restrict__ ow, const float* __restrict__ ob,
    const float* __restrict__ mw, const float* __restrict__ mb)
{
    __shared__ float wt[288 * 32];     // rows (c_local*9+kk) x 32 j

    const int tid = threadIdx.x;
    const int wid = tid >> 5, lane = tid & 31;
    const int quad = lane >> 2, jg = lane & 3;
    const int qb = lane & ~3;
    const int b = blockIdx.z;
    const int w0 = blockIdx.x * 32, h0 = blockIdx.y * 8;
    const int h = h0 + wid;
    const int aw = w0 + lane;          // gather identity: own pixel
    const int bw = w0 + quad * 4;      // output identity: quad of pixels
    const int hw0 = h * W_ + bw;
    const float* xb = x + (size_t)b * C_ * HW_;

    unsigned long long acc2[4][4];     // [px][q] -> j = jg*8 + 2q (+1 hi)
#pragma unroll
    for (int i = 0; i < 4; ++i)
#pragma unroll
        for (int q = 0; q < 4; ++q) acc2[i][q] = 0ull;

    for (int half = 0; half < 2; ++half) {
        __syncthreads();
        // stage weight half: rows ck = half*288 .. +288, swizzled [row][j]
        for (int i = tid; i < 288 * 32; i += 256) {
            const int j = i & 31;
            const int ck = half * 288 + (i >> 5);   // global c*9+kk
            float v = 0.f;
            if (j < 18)       v = ow[(size_t)j * 576 + ck];
            else if (j < 27)  v = mw[(size_t)(j - 18) * 576 + ck];
            wt[i] = v;
        }
        __syncthreads();

        for (int cl = 0; cl < 32; ++cl) {
            const float* xc = xb + (size_t)(half * 32 + cl) * HW_;
#pragma unroll
            for (int kk = 0; kk < 9; ++kk) {
                const int gy = h + (kk / 3) - 1;
                const int gx = aw + (kk % 3) - 1;
                float v = 0.f;
                if (gy >= 0 && gy < H_ && gx >= 0 && gx < W_)
                    v = __ldg(xc + gy * W_ + gx);
                // quad broadcast of 4 pixel values
                const float v0f = __shfl_sync(0xffffffffu, v, qb + 0);
                const float v1f = __shfl_sync(0xffffffffu, v, qb + 1);
                const float v2f = __shfl_sync(0xffffffffu, v, qb + 2);
                const float v3f = __shfl_sync(0xffffffffu, v, qb + 3);
                const unsigned long long v0 = pk2(v0f, v0f);
                const unsigned long long v1 = pk2(v1f, v1f);
                const unsigned long long v2 = pk2(v2f, v2f);
                const unsigned long long v3 = pk2(v3f, v3f);

                const float* wc = wt + (cl * 9 + kk) * 32 + jg * 8;
                const ulonglong2 wA = *reinterpret_cast<const ulonglong2*>(wc);
                const ulonglong2 wB = *reinterpret_cast<const ulonglong2*>(wc + 4);

                fma2(acc2[0][0], v0, wA.x); fma2(acc2[0][1], v0, wA.y);
                fma2(acc2[0][2], v0, wB.x); fma2(acc2[0][3], v0, wB.y);
                fma2(acc2[1][0], v1, wA.x); fma2(acc2[1][1], v1, wA.y);
                fma2(acc2[1][2], v1, wB.x); fma2(acc2[1][3], v1, wB.y);
                fma2(acc2[2][0], v2, wA.x); fma2(acc2[2][1], v2, wA.y);
                fma2(acc2[2][2], v2, wB.x); fma2(acc2[2][3], v2, wB.y);
                fma2(acc2[3][0], v3, wA.x); fma2(acc2[3][1], v3, wA.y);
                fma2(acc2[3][2], v3, wB.x); fma2(acc2[3][3], v3, wB.y);
            }
        }
    }

    // ---- epilogue: offsets (j<18) + modulation sigmoid mean (18<=j<27) ----
    float sig[4] = {0.f, 0.f, 0.f, 0.f};   // per-px sigmoid partial sum
#pragma unroll
    for (int q = 0; q < 4; ++q) {
        float a0[4], a1[4];
#pragma unroll
        for (int i = 0; i < 4; ++i) upk2(acc2[i][q], a0[i], a1[i]);
        const int j0 = jg * 8 + 2 * q, j1 = j0 + 1;

        if (j0 < 18) {
            const float bj = __ldg(&ob[j0]);
            float4 vv;
            vv.x = a0[0] + bj; vv.y = a0[1] + bj;
            vv.z = a0[2] + bj; vv.w = a0[3] + bj;
            *reinterpret_cast<float4*>(g_offs + ((size_t)b * 18 + j0) * HW_ + hw0) = vv;
        } else if (j0 < 27) {
            const float bj = __ldg(&mb[j0 - 18]);
#pragma unroll
            for (int i = 0; i < 4; ++i)
                sig[i] += 1.f / (1.f + __expf(-(a0[i] + bj)));
        }
        if (j1 < 18) {
            const float bj = __ldg(&ob[j1]);
            float4 vv;
            vv.x = a1[0] + bj; vv.y = a1[1] + bj;
            vv.z = a1[2] + bj; vv.w = a1[3] + bj;
            *reinterpret_cast<float4*>(g_offs + ((size_t)b * 18 + j1) * HW_ + hw0) = vv;
        } else if (j1 < 27) {
            const float bj = __ldg(&mb[j1 - 18]);
#pragma unroll
            for (int i = 0; i < 4; ++i)
                sig[i] += 1.f / (1.f + __expf(-(a1[i] + bj)));
        }
    }
    // combine modulation partials: jg=2 holds j=18..23, jg=3 holds j=24..26
    float tot[4];
#pragma unroll
    for (int i = 0; i < 4; ++i)
        tot[i] = sig[i] + __shfl_xor_sync(0xffffffffu, sig[i], 1);
    if (jg == 2) {
        float4 mmv;
        mmv.x = tot[0] * (1.f / 9.f); mmv.y = tot[1] * (1.f / 9.f);
        mmv.z = tot[2] * (1.f / 9.f); mmv.w = tot[3] * (1.f / 9.f);
        *reinterpret_cast<float4*>(g_modmean + (size_t)b * HW_ + hw0) = mmv;
    }
}

// ---------------------------------------------------------------------------
// Kernel 2 (v4, unchanged): warp-local gather+GEMM via quad shfl.
// ---------------------------------------------------------------------------
__global__ __launch_bounds__(256, 2) void k_main(
    const float* __restrict__ x,
    const float* __restrict__ bias,
    float* __restrict__ out)
{
    __shared__ float wk[64 * 64];      // [c][j] swizzled (q*16 + og*4 + e)

    const int tid = threadIdx.x;
    const int wid = tid >> 5, lane = tid & 31;
    const int quad = lane >> 2, og = lane & 3;
    const int b = blockIdx.z;
    const int w0 = blockIdx.x * 32, h0 = blockIdx.y * 8;
    const int h = h0 + wid;
    const int aw = w0 + lane;          // gather identity: own pixel
    const int ahw = h * W_ + aw;
    const int bw = w0 + quad * 4;      // GEMM identity: quad of pixels
    const int bhw0 = h * W_ + bw;
    const float* xb = x + (size_t)b * C_ * HW_;

    unsigned long long acc2[4][8];     // [px][2*q+p] <-> o = og*16 + 4q + 2p
#pragma unroll
    for (int i = 0; i < 4; ++i)
#pragma unroll
        for (int q = 0; q < 8; ++q) acc2[i][q] = 0ull;

    for (int k = 0; k < 9; ++k) {
        __syncthreads();               // previous wk fully consumed
        {
            const float4* src = reinterpret_cast<const float4*>(g_wT + k * 4096);
            float4* dst = reinterpret_cast<float4*>(wk);
#pragma unroll
            for (int i = 0; i < 4; ++i) dst[tid + 256 * i] = src[tid + 256 * i];
        }
        __syncthreads();

        const int ky = k / 3 - 1, kx = k % 3 - 1;
        const float sy = (float)(h + ky)
            + g_offs[((size_t)b * 18 + k) * HW_ + ahw];
        const float sx = (float)(aw + kx)
            + g_offs[((size_t)b * 18 + 9 + k) * HW_ + ahw];
        const float y0f = floorf(sy), x0f = floorf(sx);
        const float wy1 = sy - y0f, wx1 = sx - x0f;
        const float wy0 = 1.f - wy1, wx0 = 1.f - wx1;
        const int y0 = (int)y0f, x0 = (int)x0f;
        const bool vy0 = (y0 >= 0) & (y0 < H_);
        const bool vy1 = (y0 + 1 >= 0) & (y0 + 1 < H_);
        const bool vx0 = (x0 >= 0) & (x0 < W_);
        const bool vx1 = (x0 + 1 >= 0) & (x0 + 1 < W_);
        const float m00 = (vy0 && vx0) ? wy0 * wx0 : 0.f;
        const float m01 = (vy0 && vx1) ? wy0 * wx1 : 0.f;
        const float m10 = (vy1 && vx0) ? wy1 * wx0 : 0.f;
        const float m11 = (vy1 && vx1) ? wy1 * wx1 : 0.f;
        const int cy0 = min(max(y0, 0), H_ - 1);
        const int cy1 = min(max(y0 + 1, 0), H_ - 1);
        const int cx0 = min(max(x0, 0), W_ - 1);
        const int cx1 = min(max(x0 + 1, 0), W_ - 1);
        const int i00 = cy0 * W_ + cx0, i01 = cy0 * W_ + cx1;
        const int i10 = cy1 * W_ + cx0, i11 = cy1 * W_ + cx1;
        const int qb = lane & ~3;      // quad base lane

#pragma unroll 4
        for (int c = 0; c < 64; ++c) {
            const float* xc = xb + (size_t)c * HW_;
            const float v = m00 * __ldg(xc + i00) + m01 * __ldg(xc + i01)
                          + m10 * __ldg(xc + i10) + m11 * __ldg(xc + i11);
            const float v0f = __shfl_sync(0xffffffffu, v, qb + 0);
            const float v1f = __shfl_sync(0xffffffffu, v, qb + 1);
            const float v2f = __shfl_sync(0xffffffffu, v, qb + 2);
            const float v3f = __shfl_sync(0xffffffffu, v, qb + 3);
            const unsigned long long v0 = pk2(v0f, v0f);
            const unsigned long long v1 = pk2(v1f, v1f);
            const unsigned long long v2 = pk2(v2f, v2f);
            const unsigned long long v3 = pk2(v3f, v3f);

            const float* wc = wk + c * 64 + og * 4;
            const ulonglong2 wA = *reinterpret_cast<const ulonglong2*>(wc);
            const ulonglong2 wB = *reinterpret_cast<const ulonglong2*>(wc + 16);
            const ulonglong2 wC = *reinterpret_cast<const ulonglong2*>(wc + 32);
            const ulonglong2 wD = *reinterpret_cast<const ulonglong2*>(wc + 48);

            fma2(acc2[0][0], v0, wA.x); fma2(acc2[0][1], v0, wA.y);
            fma2(acc2[0][2], v0, wB.x); fma2(acc2[0][3], v0, wB.y);
            fma2(acc2[0][4], v0, wC.x); fma2(acc2[0][5], v0, wC.y);
            fma2(acc2[0][6], v0, wD.x); fma2(acc2[0][7], v0, wD.y);
            fma2(acc2[1][0], v1, wA.x); fma2(acc2[1][1], v1, wA.y);
            fma2(acc2[1][2], v1, wB.x); fma2(acc2[1][3], v1, wB.y);
            fma2(acc2[1][4], v1, wC.x); fma2(acc2[1][5], v1, wC.y);
            fma2(acc2[1][6], v1, wD.x); fma2(acc2[1][7], v1, wD.y);
            fma2(acc2[2][0], v2, wA.x); fma2(acc2[2][1], v2, wA.y);
            fma2(acc2[2][2], v2, wB.x); fma2(acc2[2][3], v2, wB.y);
            fma2(acc2[2][4], v2, wC.x); fma2(acc2[2][5], v2, wC.y);
            fma2(acc2[2][6], v2, wD.x); fma2(acc2[2][7], v2, wD.y);
            fma2(acc2[3][0], v3, wA.x); fma2(acc2[3][1], v3, wA.y);
            fma2(acc2[3][2], v3, wB.x); fma2(acc2[3][3], v3, wB.y);
            fma2(acc2[3][4], v3, wC.x); fma2(acc2[3][5], v3, wC.y);
            fma2(acc2[3][6], v3, wD.x); fma2(acc2[3][7], v3, wD.y);
        }
    }

    float mm[4];
#pragma unroll
    for (int i = 0; i < 4; ++i) mm[i] = g_modmean[(size_t)b * HW_ + bhw0 + i];

#pragma unroll
    for (int q = 0; q < 4; ++q) {
#pragma unroll
        for (int p = 0; p < 2; ++p) {
            float a0[4], a1[4];
#pragma unroll
            for (int i = 0; i < 4; ++i) upk2(acc2[i][2 * q + p], a0[i], a1[i]);
            const int oa = og * 16 + 4 * q + 2 * p, ob2 = oa + 1;
            const float ba = __ldg(&bias[oa]), bb = __ldg(&bias[ob2]);
            float4 va, vb;
            va.x = fmaf(a0[0], mm[0], ba); va.y = fmaf(a0[1], mm[1], ba);
            va.z = fmaf(a0[2], mm[2], ba); va.w = fmaf(a0[3], mm[3], ba);
            vb.x = fmaf(a1[0], mm[0], bb); vb.y = fmaf(a1[1], mm[1], bb);
            vb.z = fmaf(a1[2], mm[2], bb); vb.w = fmaf(a1[3], mm[3], bb);
            *reinterpret_cast<float4*>(out + ((size_t)b * 64 + oa) * HW_ + bhw0) = va;
            *reinterpret_cast<float4*>(out + ((size_t)b * 64 + ob2) * HW_ + bhw0) = vb;
        }
    }
}

// ---------------------------------------------------------------------------
// Launch order: k_offmod first (ncu capture slot; needs only inputs), then
// k_wprep, then k_main (needs g_offs + g_wT).
// ---------------------------------------------------------------------------
extern "C" void kernel_launch(void* const* d_in, const int* in_sizes, int n_in,
                              void* d_out, int out_size)
{
    const float* x      = (const float*)d_in[0];
    const float* weight = (const float*)d_in[1];
    const float* bias   = (const float*)d_in[2];
    const float* ow     = (const float*)d_in[3];
    const float* ob     = (const float*)d_in[4];
    const float* mw     = (const float*)d_in[5];
    const float* mb     = (const float*)d_in[6];
    float* out = (float*)d_out;

    dim3 grd(W_ / 32, H_ / 8, B_);
    k_offmod<<<grd, 256>>>(x, ow, ob, mw, mb);

    k_wprep<<<(9 * 64 * 64 + 255) / 256, 256>>>(weight);

    k_main<<<grd, 256>>>(x, bias, out);
}